// round 13
// baseline (speedup 1.0000x reference)
#include <cuda_runtime.h>
#include <cuda_fp16.h>
#include <mma.h>
#include <math.h>
#include <cstdint>

using namespace nvcuda;

#define NN    50000
#define EE    800000
#define ET    (EE + NN)
#define IND   256
#define HID   32
#define HEADS 4
#define HH    (HEADS * HID)      // 128
#define SLOPE 0.2f

// gemm1 tiling
#define BM    128
#define BK    32
#define NK    (IND / BK)         // 8 K-steps
#define XSTR  (BK + 4)           // 36
#define WSTR  (HH + 4)           // 132
#define OSTR  (HH + 4)           // 132
#define XS_ELEMS (BM * XSTR)     // 4608 floats / stage
#define WS_ELEMS (BK * WSTR)     // 4224 floats / stage
#define GEMM1_SMEM ((2 * XS_ELEMS + 2 * WS_ELEMS) * 4)   // 70656 B (>= 67584 epilogue)

#define SCAN_B 196               // ceil(50000/256)

// ---------------- scratch ----------------
__device__ __half d_h1h[NN * HH];   // fp16 h1 for gather
__device__ float d_as1[NN * HEADS];
__device__ float d_ad1[NN * HEADS];
__device__ float d_out1[NN * HH];

__device__ __half d_h2h[NN * HID];  // fp16 h2 for gather
__device__ float d_as2[NN];
__device__ float d_ad2[NN];

// CSR scratch: [0,NN) = histogram counts, [NN,2NN) = scatter cursors
// Both banks are zero at kernel_launch entry: zero-initialized at load,
// and k_scanBC re-zeroes them every run (after scanA consumes counts,
// before scatter uses cursors).
__device__ int d_cnt   [2 * NN];
__device__ int d_rowptr[NN + 1];
__device__ int d_esrc  [ET];
__device__ int d_bsum  [256];

// ---------------- helpers ----------------
__device__ __forceinline__ float lrelu(float v) { return v > 0.0f ? v : SLOPE * v; }
__device__ __forceinline__ float eluf (float v) { return v > 0.0f ? v : __expf(v) - 1.0f; }

__device__ __forceinline__ void cpasync16(unsigned int dst, const void* src, int src_bytes) {
    asm volatile("cp.async.cg.shared.global [%0], [%1], 16, %2;"
                 :: "r"(dst), "l"(src), "r"(src_bytes));
}
__device__ __forceinline__ unsigned int smem_u32(const void* p) {
    return (unsigned int)__cvta_generic_to_shared(p);
}

// ---------------- CSR build ----------------
__global__ void k_hist(const int* __restrict__ ei) {
    int e = blockIdx.x * blockDim.x + threadIdx.x;
    if (e < EE) atomicAdd(&d_cnt[ei[EE + e]], 1);
}

__global__ void k_scanA() {
    __shared__ int sh[256];
    int t = threadIdx.x;
    int idx = blockIdx.x * 256 + t;
    int c = (idx < NN) ? (d_cnt[idx] + 1) : 0;   // +1: self loop
    sh[t] = c;
    __syncthreads();
#pragma unroll
    for (int off = 1; off < 256; off <<= 1) {
        int v = (t >= off) ? sh[t - off] : 0;
        __syncthreads();
        sh[t] += v;
        __syncthreads();
    }
    if (idx < NN) d_rowptr[idx] = sh[t] - c;
    if (t == 255) d_bsum[blockIdx.x] = sh[255];
}

// fused: per-block reduction over preceding block sums + offset add + counter re-zero
__global__ void k_scanBC() {
    __shared__ int sh[256];
    int t = threadIdx.x;
    int b = blockIdx.x;
    sh[t] = (t < b) ? d_bsum[t] : 0;    // b <= 195 < 256
    __syncthreads();
#pragma unroll
    for (int off = 128; off; off >>= 1) {
        if (t < off) sh[t] += sh[t + off];
        __syncthreads();
    }
    int pref = sh[0];
    int idx = b * 256 + t;
    if (idx < NN) {
        d_rowptr[idx] += pref;
        d_cnt[idx] = 0;          // hist bank: clean for NEXT run
        d_cnt[NN + idx] = 0;     // cursor bank: clean for scatter THIS run
    }
    if (idx == 0) d_rowptr[NN] = ET;
}

__global__ void k_scatter(const int* __restrict__ ei) {
    int id = blockIdx.x * blockDim.x + threadIdx.x;
    if (id >= ET) return;
    int s, d;
    if (id < EE) { s = ei[id]; d = ei[EE + id]; }
    else         { s = id - EE; d = id - EE; }
    int pos = d_rowptr[d] + atomicAdd(&d_cnt[NN + d], 1);
    d_esrc[pos] = s;
}

// ---------------- layer 1: TF32 wmma GEMM, cp.async double-buffered ----------------
// 256 threads = 8 warps, 4(M) x 2(N); warp tile 32x64 = 2x4 m16n16k8 frags
__global__ void __launch_bounds__(256) k_gemm1(
        const float* __restrict__ x, const float* __restrict__ W,
        const float* __restrict__ att_s, const float* __restrict__ att_d) {
    extern __shared__ float smem[];
    float* xs[2] = { smem, smem + XS_ELEMS };
    float* ws[2] = { smem + 2 * XS_ELEMS, smem + 2 * XS_ELEMS + WS_ELEMS };
    float* os = smem;   // epilogue reuse

    int tid  = threadIdx.x;
    int wid  = tid >> 5, lane = tid & 31;
    int n0   = blockIdx.x * BM;
    int wm   = wid & 3;
    int wn   = wid >> 2;

    int xrow = tid >> 1;                 // 0..127
    int xq0  = (tid & 1) * 4;            // f4 col base
    int wrow = tid >> 3;                 // 0..31
    int wq0  = (tid & 7) * 4;            // f4 col base

    auto issue_stage = [&](int st, int k0) {
        const float* xsrc = &x[(size_t)(n0 + xrow) * IND + k0 + xq0 * 4];
        int ok = (n0 + xrow < NN) ? 16 : 0;
        unsigned int xdst = smem_u32(&xs[st][xrow * XSTR + xq0 * 4]);
#pragma unroll
        for (int i = 0; i < 4; i++)
            cpasync16(xdst + i * 16, xsrc + i * 4, ok);
        const float* wsrc = &W[(size_t)(k0 + wrow) * HH + wq0 * 4];
        unsigned int wdst = smem_u32(&ws[st][wrow * WSTR + wq0 * 4]);
#pragma unroll
        for (int i = 0; i < 4; i++)
            cpasync16(wdst + i * 16, wsrc + i * 4, 16);
        asm volatile("cp.async.commit_group;");
    };

    // round own staged elements to tf32 (round-to-nearest) in place
    auto round_stage = [&](int st) {
        float* xp = &xs[st][xrow * XSTR + xq0 * 4];
#pragma unroll
        for (int i = 0; i < 4; i++) {
            float4 v = *(float4*)(xp + i * 4);
            v.x = wmma::__float_to_tf32(v.x);
            v.y = wmma::__float_to_tf32(v.y);
            v.z = wmma::__float_to_tf32(v.z);
            v.w = wmma::__float_to_tf32(v.w);
            *(float4*)(xp + i * 4) = v;
        }
        float* wp = &ws[st][wrow * WSTR + wq0 * 4];
#pragma unroll
        for (int i = 0; i < 4; i++) {
            float4 v = *(float4*)(wp + i * 4);
            v.x = wmma::__float_to_tf32(v.x);
            v.y = wmma::__float_to_tf32(v.y);
            v.z = wmma::__float_to_tf32(v.z);
            v.w = wmma::__float_to_tf32(v.w);
            *(float4*)(wp + i * 4) = v;
        }
    };

    wmma::fragment<wmma::accumulator, 16, 16, 8, float> c[2][4];
#pragma unroll
    for (int i = 0; i < 2; i++)
#pragma unroll
        for (int j = 0; j < 4; j++) wmma::fill_fragment(c[i][j], 0.0f);

    issue_stage(0, 0);

    for (int kt = 0; kt < NK; kt++) {
        int st = kt & 1;
        if (kt + 1 < NK) {
            issue_stage(st ^ 1, (kt + 1) * BK);
            asm volatile("cp.async.wait_group 1;");
        } else {
            asm volatile("cp.async.wait_group 0;");
        }
        __syncthreads();
        round_stage(st);
        __syncthreads();

#pragma unroll
        for (int kk = 0; kk < BK; kk += 8) {
            wmma::fragment<wmma::matrix_a, 16, 16, 8, wmma::precision::tf32, wmma::row_major> a[2];
            wmma::fragment<wmma::matrix_b, 16, 16, 8, wmma::precision::tf32, wmma::row_major> b[4];
#pragma unroll
            for (int i = 0; i < 2; i++)
                wmma::load_matrix_sync(a[i], &xs[st][(wm * 32 + i * 16) * XSTR + kk], XSTR);
#pragma unroll
            for (int j = 0; j < 4; j++)
                wmma::load_matrix_sync(b[j], &ws[st][kk * WSTR + wn * 64 + j * 16], WSTR);
#pragma unroll
            for (int i = 0; i < 2; i++)
#pragma unroll
                for (int j = 0; j < 4; j++)
                    wmma::mma_sync(c[i][j], a[i], b[j], c[i][j]);
        }
        __syncthreads();
    }

    // stage accumulators in smem
#pragma unroll
    for (int i = 0; i < 2; i++)
#pragma unroll
        for (int j = 0; j < 4; j++)
            wmma::store_matrix_sync(&os[(wm * 32 + i * 16) * OSTR + wn * 64 + j * 16],
                                    c[i][j], OSTR, wmma::mem_row_major);
    __syncthreads();

    // epilogue: fp16 h1 write + attention scalars
    int head = wid & 3;
    int rofs = wid >> 2;
    float es = att_s[head * HID + lane];
    float ed = att_d[head * HID + lane];
#pragma unroll 4
    for (int r2 = 0; r2 < BM; r2 += 2) {
        int r = r2 + rofs;
        int n = n0 + r;
        if (n >= NN) continue;
        float v = os[r * OSTR + head * 32 + lane];
        d_h1h[(size_t)n * HH + head * 32 + lane] = __float2half_rn(v);
        float s = v * es, t = v * ed;
#pragma unroll
        for (int o = 16; o; o >>= 1) {
            s += __shfl_xor_sync(0xffffffffu, s, o);
            t += __shfl_xor_sync(0xffffffffu, t, o);
        }
        if (lane == 0) { d_as1[n * HEADS + head] = s; d_ad1[n * HEADS + head] = t; }
    }
}

// ---------------- layer 1: CSR gather (fp16 rows, chunked shuffle) ----------------
__global__ void k_gather1(const float* __restrict__ b1) {
    int gid  = blockIdx.x * blockDim.x + threadIdx.x;
    int n    = gid >> 5;
    if (n >= NN) return;
    int lane = gid & 31;
    int h    = lane >> 3;

    int start = d_rowptr[n], end = d_rowptr[n + 1];
    float ad = d_ad1[n * 4 + h];

    float4 acc = make_float4(0.f, 0.f, 0.f, 0.f);
    float  den = 0.f;

    for (int base = start; base < end; base += 32) {
        int m   = min(32, end - base);
        int myS = (lane < m) ? __ldg(&d_esrc[base + lane]) : 0;
#pragma unroll 4
        for (int i = 0; i < m; i++) {
            int s = __shfl_sync(0xffffffffu, myS, i);
            float p = __expf(lrelu(__ldg(&d_as1[s * 4 + h]) + ad));
            uint2 raw = *(const uint2*)&d_h1h[(size_t)s * HH + lane * 4];
            float2 f01 = __half22float2(*(__half2*)&raw.x);
            float2 f23 = __half22float2(*(__half2*)&raw.y);
            den  += p;
            acc.x = fmaf(p, f01.x, acc.x);
            acc.y = fmaf(p, f01.y, acc.y);
            acc.z = fmaf(p, f23.x, acc.z);
            acc.w = fmaf(p, f23.y, acc.w);
        }
    }

    float inv = 1.0f / den;
    float4 bb = *(const float4*)&b1[lane * 4];
    acc.x = eluf(acc.x * inv + bb.x);
    acc.y = eluf(acc.y * inv + bb.y);
    acc.z = eluf(acc.z * inv + bb.z);
    acc.w = eluf(acc.w * inv + bb.w);
    *(float4*)&d_out1[(size_t)n * HH + lane * 4] = acc;
}

// ---------------- layer 2: GEMM (32 nodes/block) + attention scalars ----------------
__global__ void k_gemm2(const float* __restrict__ W2,
                        const float* __restrict__ att_s, const float* __restrict__ att_d) {
    __shared__ float Ws[HH * HID];    // 16 KB
    __shared__ float xs[32][HH];      // 16 KB
    int tid = threadIdx.x;
    for (int t = tid; t < HH * HID; t += 256) Ws[t] = W2[t];
    int w = tid >> 5, lane = tid & 31;
    int n0 = blockIdx.x * 32;
#pragma unroll
    for (int r = 0; r < 4; r++) {
        int row = w * 4 + r;
        int n = n0 + row;
        if (n < NN)
            *(float4*)&xs[row][lane * 4] = *(const float4*)&d_out1[(size_t)n * HH + lane * 4];
    }
    __syncthreads();

    float as_l = att_s[lane], ad_l = att_d[lane];
#pragma unroll
    for (int r = 0; r < 4; r++) {
        int row = w * 4 + r;
        int n = n0 + row;
        if (n >= NN) break;
        float acc = 0.0f;
#pragma unroll 8
        for (int k = 0; k < HH; k += 4) {
            float4 xv = *(const float4*)&xs[row][k];
            acc += xv.x * Ws[(k + 0) * HID + lane];
            acc += xv.y * Ws[(k + 1) * HID + lane];
            acc += xv.z * Ws[(k + 2) * HID + lane];
            acc += xv.w * Ws[(k + 3) * HID + lane];
        }
        d_h2h[n * HID + lane] = __float2half_rn(acc);
        float s = acc * as_l, t = acc * ad_l;
#pragma unroll
        for (int o = 16; o; o >>= 1) {
            s += __shfl_xor_sync(0xffffffffu, s, o);
            t += __shfl_xor_sync(0xffffffffu, t, o);
        }
        if (lane == 0) { d_as2[n] = s; d_ad2[n] = t; }
    }
}

// ---------------- layer 2: CSR gather + bias/ELU + classifier ----------------
__global__ void k_gather2(const float* __restrict__ b2, const float* __restrict__ lw,
                          const float* __restrict__ lb, float* __restrict__ out) {
    int gid  = blockIdx.x * blockDim.x + threadIdx.x;
    int n    = gid >> 5;
    if (n >= NN) return;
    int lane = gid & 31;

    int start = d_rowptr[n], end = d_rowptr[n + 1];
    float ad = d_ad2[n];

    float acc = 0.f, den = 0.f;
    for (int base = start; base < end; base += 32) {
        int m   = min(32, end - base);
        int myS = (lane < m) ? __ldg(&d_esrc[base + lane]) : 0;
        float myA = (lane < m) ? __ldg(&d_as2[myS]) : 0.f;
#pragma unroll 4
        for (int i = 0; i < m; i++) {
            int   s  = __shfl_sync(0xffffffffu, myS, i);
            float as = __shfl_sync(0xffffffffu, myA, i);
            float p  = __expf(lrelu(as + ad));
            den += p;
            acc = fmaf(p, __half2float(d_h2h[s * HID + lane]), acc);
        }
    }

    float v = eluf(acc / den + b2[lane]);
    float o0 = v * lw[lane * 2 + 0];
    float o1 = v * lw[lane * 2 + 1];
#pragma unroll
    for (int o = 16; o; o >>= 1) {
        o0 += __shfl_xor_sync(0xffffffffu, o0, o);
        o1 += __shfl_xor_sync(0xffffffffu, o1, o);
    }
    if (lane == 0) { out[n * 2 + 0] = o0 + lb[0]; out[n * 2 + 1] = o1 + lb[1]; }
}

// ---------------- launch ----------------
extern "C" void kernel_launch(void* const* d_in, const int* in_sizes, int n_in,
                              void* d_out, int out_size) {
    const float* x        = (const float*)d_in[0];
    const int*   ei       = (const int*)  d_in[1];
    const float* W1       = (const float*)d_in[2];
    const float* att_src1 = (const float*)d_in[3];
    const float* att_dst1 = (const float*)d_in[4];
    const float* b1       = (const float*)d_in[5];
    const float* W2       = (const float*)d_in[6];
    const float* att_src2 = (const float*)d_in[7];
    const float* att_dst2 = (const float*)d_in[8];
    const float* b2       = (const float*)d_in[9];
    const float* lin_w    = (const float*)d_in[10];
    const float* lin_b    = (const float*)d_in[11];
    float* out = (float*)d_out;
    (void)in_sizes; (void)n_in; (void)out_size;

    const int GW = (NN * 32 + 255) / 256;

    static cudaStream_t s2 = nullptr;
    static cudaEvent_t evFork = nullptr, evJoin = nullptr;
    static bool inited = false;
    if (!inited) {
        cudaFuncSetAttribute(k_gemm1, cudaFuncAttributeMaxDynamicSharedMemorySize, GEMM1_SMEM);
        cudaStreamCreateWithFlags(&s2, cudaStreamNonBlocking);
        cudaEventCreateWithFlags(&evFork, cudaEventDisableTiming);
        cudaEventCreateWithFlags(&evJoin, cudaEventDisableTiming);
        inited = true;
    }

    // fork: gemm1 (independent of CSR) on side stream
    cudaEventRecord(evFork, 0);
    cudaStreamWaitEvent(s2, evFork, 0);
    k_gemm1<<<(NN + BM - 1) / BM, 256, GEMM1_SMEM, s2>>>(x, W1, att_src1, att_dst1);
    cudaEventRecord(evJoin, s2);

    // CSR build on stream 0 (counters are zero on entry; scanBC re-zeroes)
    k_hist<<<(EE + 255) / 256, 256>>>(ei);
    k_scanA<<<SCAN_B, 256>>>();
    k_scanBC<<<SCAN_B, 256>>>();
    k_scatter<<<(ET + 255) / 256, 256>>>(ei);

    // join: gather1 needs gemm1 + CSR
    cudaStreamWaitEvent(0, evJoin, 0);
    k_gather1<<<GW, 256>>>(b1);

    // layer 2
    k_gemm2<<<(NN + 31) / 32, 256>>>(W2, att_src2, att_dst2);
    k_gather2<<<GW, 256>>>(b2, lin_w, lin_b, out);
}

// round 14
// speedup vs baseline: 1.1653x; 1.1653x over previous
#include <cuda_runtime.h>
#include <cuda_fp16.h>
#include <mma.h>
#include <math.h>
#include <cstdint>

using namespace nvcuda;

#define NN    50000
#define EE    800000
#define ET    (EE + NN)
#define IND   256
#define HID   32
#define HEADS 4
#define HH    (HEADS * HID)      // 128
#define SLOPE 0.2f

// gemm1 tiling (round-8 proven config)
#define BM    128
#define BK    32
#define XSTR  (BK + 4)           // 36
#define WSTR  (HH + 4)           // 132
#define OSTR  (HH + 4)           // 132
#define GEMM1_SMEM (BM * OSTR * 4)   // 67584 B (epilogue dominates; mainloop 35328 B)

#define SCAN_B 196               // ceil(50000/256)

// ---------------- scratch ----------------
__device__ __half d_h1h[NN * HH];   // fp16 h1 for gather
__device__ float d_as1[NN * HEADS];
__device__ float d_ad1[NN * HEADS];
__device__ float d_out1[NN * HH];

__device__ __half d_h2h[NN * HID];  // fp16 h2 for gather
__device__ float d_as2[NN];
__device__ float d_ad2[NN];

// CSR scratch: [0,NN) = histogram counts, [NN,2NN) = scatter cursors
// Both banks are zero at entry (zero-init at load; scanBC re-zeroes each run).
__device__ int d_cnt   [2 * NN];
__device__ int d_rowptr[NN + 1];
__device__ int d_esrc  [ET];
__device__ int d_bsum  [256];

// ---------------- helpers ----------------
__device__ __forceinline__ float lrelu(float v) { return v > 0.0f ? v : SLOPE * v; }
__device__ __forceinline__ float eluf (float v) { return v > 0.0f ? v : __expf(v) - 1.0f; }

// ---------------- CSR build ----------------
__global__ void k_hist(const int* __restrict__ ei) {
    int e = blockIdx.x * blockDim.x + threadIdx.x;
    if (e < EE) atomicAdd(&d_cnt[ei[EE + e]], 1);
}

__global__ void k_scanA() {
    __shared__ int sh[256];
    int t = threadIdx.x;
    int idx = blockIdx.x * 256 + t;
    int c = (idx < NN) ? (d_cnt[idx] + 1) : 0;   // +1: self loop
    sh[t] = c;
    __syncthreads();
#pragma unroll
    for (int off = 1; off < 256; off <<= 1) {
        int v = (t >= off) ? sh[t - off] : 0;
        __syncthreads();
        sh[t] += v;
        __syncthreads();
    }
    if (idx < NN) d_rowptr[idx] = sh[t] - c;
    if (t == 255) d_bsum[blockIdx.x] = sh[255];
}

// fused: reduction over preceding block sums + offset add + counter re-zero
__global__ void k_scanBC() {
    __shared__ int sh[256];
    int t = threadIdx.x;
    int b = blockIdx.x;
    sh[t] = (t < b) ? d_bsum[t] : 0;    // b <= 195 < 256
    __syncthreads();
#pragma unroll
    for (int off = 128; off; off >>= 1) {
        if (t < off) sh[t] += sh[t + off];
        __syncthreads();
    }
    int pref = sh[0];
    int idx = b * 256 + t;
    if (idx < NN) {
        d_rowptr[idx] += pref;
        d_cnt[idx] = 0;          // hist bank: clean for NEXT run
        d_cnt[NN + idx] = 0;     // cursor bank: clean for scatter THIS run
    }
    if (idx == 0) d_rowptr[NN] = ET;
}

__global__ void k_scatter(const int* __restrict__ ei) {
    int id = blockIdx.x * blockDim.x + threadIdx.x;
    if (id >= ET) return;
    int s, d;
    if (id < EE) { s = ei[id]; d = ei[EE + id]; }
    else         { s = id - EE; d = id - EE; }
    int pos = d_rowptr[d] + atomicAdd(&d_cnt[NN + d], 1);
    d_esrc[pos] = s;
}

// ---------------- layer 1: TF32 wmma GEMM (round-8 config) + attention scalars ----------------
// 256 threads = 8 warps, 4(M) x 2(N); warp tile 32x64 = 2x4 m16n16k8 frags
__global__ void __launch_bounds__(256) k_gemm1(
        const float* __restrict__ x, const float* __restrict__ W,
        const float* __restrict__ att_s, const float* __restrict__ att_d) {
    extern __shared__ float smem[];
    float* xs = smem;                    // [BM][XSTR]
    float* ws = smem + BM * XSTR;        // [BK][WSTR]
    float* os = smem;                    // reused after mainloop: [BM][OSTR]

    int tid  = threadIdx.x;
    int wid  = tid >> 5, lane = tid & 31;
    int n0   = blockIdx.x * BM;
    int wm   = wid & 3;
    int wn   = wid >> 2;

    wmma::fragment<wmma::accumulator, 16, 16, 8, float> c[2][4];
#pragma unroll
    for (int i = 0; i < 2; i++)
#pragma unroll
        for (int j = 0; j < 4; j++) wmma::fill_fragment(c[i][j], 0.0f);

    for (int k0 = 0; k0 < IND; k0 += BK) {
        // x tile: 128 rows x 32 cols = 1024 float4 (inline tf32-RN conversion)
#pragma unroll
        for (int it = 0; it < 4; it++) {
            int i   = tid + it * 256;
            int row = i >> 3, kq = i & 7;
            int n   = n0 + row;
            float4 v = make_float4(0.f, 0.f, 0.f, 0.f);
            if (n < NN) v = *(const float4*)&x[(size_t)n * IND + k0 + kq * 4];
            v.x = wmma::__float_to_tf32(v.x);
            v.y = wmma::__float_to_tf32(v.y);
            v.z = wmma::__float_to_tf32(v.z);
            v.w = wmma::__float_to_tf32(v.w);
            *(float4*)&xs[row * XSTR + kq * 4] = v;
        }
        // W tile: 32 rows x 128 cols = 1024 float4
#pragma unroll
        for (int it = 0; it < 4; it++) {
            int i  = tid + it * 256;
            int k  = i >> 5, nq = i & 31;
            float4 v = *(const float4*)&W[(size_t)(k0 + k) * HH + nq * 4];
            v.x = wmma::__float_to_tf32(v.x);
            v.y = wmma::__float_to_tf32(v.y);
            v.z = wmma::__float_to_tf32(v.z);
            v.w = wmma::__float_to_tf32(v.w);
            *(float4*)&ws[k * WSTR + nq * 4] = v;
        }
        __syncthreads();

#pragma unroll
        for (int kk = 0; kk < BK; kk += 8) {
            wmma::fragment<wmma::matrix_a, 16, 16, 8, wmma::precision::tf32, wmma::row_major> a[2];
            wmma::fragment<wmma::matrix_b, 16, 16, 8, wmma::precision::tf32, wmma::row_major> b[4];
#pragma unroll
            for (int i = 0; i < 2; i++)
                wmma::load_matrix_sync(a[i], &xs[(wm * 32 + i * 16) * XSTR + kk], XSTR);
#pragma unroll
            for (int j = 0; j < 4; j++)
                wmma::load_matrix_sync(b[j], &ws[kk * WSTR + wn * 64 + j * 16], WSTR);
#pragma unroll
            for (int i = 0; i < 2; i++)
#pragma unroll
                for (int j = 0; j < 4; j++)
                    wmma::mma_sync(c[i][j], a[i], b[j], c[i][j]);
        }
        __syncthreads();
    }

    // stage accumulators in smem (xs/ws dead)
#pragma unroll
    for (int i = 0; i < 2; i++)
#pragma unroll
        for (int j = 0; j < 4; j++)
            wmma::store_matrix_sync(&os[(wm * 32 + i * 16) * OSTR + wn * 64 + j * 16],
                                    c[i][j], OSTR, wmma::mem_row_major);
    __syncthreads();

    // epilogue: fp16 h1 write + attention scalars
    int head = wid & 3;
    int rofs = wid >> 2;
    float es = att_s[head * HID + lane];
    float ed = att_d[head * HID + lane];
#pragma unroll 4
    for (int r2 = 0; r2 < BM; r2 += 2) {
        int r = r2 + rofs;
        int n = n0 + r;
        if (n >= NN) continue;
        float v = os[r * OSTR + head * 32 + lane];
        d_h1h[(size_t)n * HH + head * 32 + lane] = __float2half_rn(v);
        float s = v * es, t = v * ed;
#pragma unroll
        for (int o = 16; o; o >>= 1) {
            s += __shfl_xor_sync(0xffffffffu, s, o);
            t += __shfl_xor_sync(0xffffffffu, t, o);
        }
        if (lane == 0) { d_as1[n * HEADS + head] = s; d_ad1[n * HEADS + head] = t; }
    }
}

// ---------------- layer 1: CSR gather (fp16 rows, chunked shuffle) ----------------
__global__ void k_gather1(const float* __restrict__ b1) {
    int gid  = blockIdx.x * blockDim.x + threadIdx.x;
    int n    = gid >> 5;
    if (n >= NN) return;
    int lane = gid & 31;
    int h    = lane >> 3;

    int start = d_rowptr[n], end = d_rowptr[n + 1];
    float ad = d_ad1[n * 4 + h];

    float4 acc = make_float4(0.f, 0.f, 0.f, 0.f);
    float  den = 0.f;

    for (int base = start; base < end; base += 32) {
        int m   = min(32, end - base);
        int myS = (lane < m) ? __ldg(&d_esrc[base + lane]) : 0;
#pragma unroll 4
        for (int i = 0; i < m; i++) {
            int s = __shfl_sync(0xffffffffu, myS, i);
            float p = __expf(lrelu(__ldg(&d_as1[s * 4 + h]) + ad));
            uint2 raw = *(const uint2*)&d_h1h[(size_t)s * HH + lane * 4];
            float2 f01 = __half22float2(*(__half2*)&raw.x);
            float2 f23 = __half22float2(*(__half2*)&raw.y);
            den  += p;
            acc.x = fmaf(p, f01.x, acc.x);
            acc.y = fmaf(p, f01.y, acc.y);
            acc.z = fmaf(p, f23.x, acc.z);
            acc.w = fmaf(p, f23.y, acc.w);
        }
    }

    float inv = 1.0f / den;
    float4 bb = *(const float4*)&b1[lane * 4];
    acc.x = eluf(acc.x * inv + bb.x);
    acc.y = eluf(acc.y * inv + bb.y);
    acc.z = eluf(acc.z * inv + bb.z);
    acc.w = eluf(acc.w * inv + bb.w);
    *(float4*)&d_out1[(size_t)n * HH + lane * 4] = acc;
}

// ---------------- layer 2: GEMM (32 nodes/block) + attention scalars ----------------
__global__ void k_gemm2(const float* __restrict__ W2,
                        const float* __restrict__ att_s, const float* __restrict__ att_d) {
    __shared__ float Ws[HH * HID];    // 16 KB
    __shared__ float xs[32][HH];      // 16 KB
    int tid = threadIdx.x;
    for (int t = tid; t < HH * HID; t += 256) Ws[t] = W2[t];
    int w = tid >> 5, lane = tid & 31;
    int n0 = blockIdx.x * 32;
#pragma unroll
    for (int r = 0; r < 4; r++) {
        int row = w * 4 + r;
        int n = n0 + row;
        if (n < NN)
            *(float4*)&xs[row][lane * 4] = *(const float4*)&d_out1[(size_t)n * HH + lane * 4];
    }
    __syncthreads();

    float as_l = att_s[lane], ad_l = att_d[lane];
#pragma unroll
    for (int r = 0; r < 4; r++) {
        int row = w * 4 + r;
        int n = n0 + row;
        if (n >= NN) break;
        float acc = 0.0f;
#pragma unroll 8
        for (int k = 0; k < HH; k += 4) {
            float4 xv = *(const float4*)&xs[row][k];
            acc += xv.x * Ws[(k + 0) * HID + lane];
            acc += xv.y * Ws[(k + 1) * HID + lane];
            acc += xv.z * Ws[(k + 2) * HID + lane];
            acc += xv.w * Ws[(k + 3) * HID + lane];
        }
        d_h2h[n * HID + lane] = __float2half_rn(acc);
        float s = acc * as_l, t = acc * ad_l;
#pragma unroll
        for (int o = 16; o; o >>= 1) {
            s += __shfl_xor_sync(0xffffffffu, s, o);
            t += __shfl_xor_sync(0xffffffffu, t, o);
        }
        if (lane == 0) { d_as2[n] = s; d_ad2[n] = t; }
    }
}

// ---------------- layer 2: CSR gather + bias/ELU + classifier ----------------
__global__ void k_gather2(const float* __restrict__ b2, const float* __restrict__ lw,
                          const float* __restrict__ lb, float* __restrict__ out) {
    int gid  = blockIdx.x * blockDim.x + threadIdx.x;
    int n    = gid >> 5;
    if (n >= NN) return;
    int lane = gid & 31;

    int start = d_rowptr[n], end = d_rowptr[n + 1];
    float ad = d_ad2[n];

    float acc = 0.f, den = 0.f;
    for (int base = start; base < end; base += 32) {
        int m   = min(32, end - base);
        int myS = (lane < m) ? __ldg(&d_esrc[base + lane]) : 0;
        float myA = (lane < m) ? __ldg(&d_as2[myS]) : 0.f;
#pragma unroll 4
        for (int i = 0; i < m; i++) {
            int   s  = __shfl_sync(0xffffffffu, myS, i);
            float as = __shfl_sync(0xffffffffu, myA, i);
            float p  = __expf(lrelu(as + ad));
            den += p;
            acc = fmaf(p, __half2float(d_h2h[s * HID + lane]), acc);
        }
    }

    float v = eluf(acc / den + b2[lane]);
    float o0 = v * lw[lane * 2 + 0];
    float o1 = v * lw[lane * 2 + 1];
#pragma unroll
    for (int o = 16; o; o >>= 1) {
        o0 += __shfl_xor_sync(0xffffffffu, o0, o);
        o1 += __shfl_xor_sync(0xffffffffu, o1, o);
    }
    if (lane == 0) { out[n * 2 + 0] = o0 + lb[0]; out[n * 2 + 1] = o1 + lb[1]; }
}

// ---------------- launch ----------------
extern "C" void kernel_launch(void* const* d_in, const int* in_sizes, int n_in,
                              void* d_out, int out_size) {
    const float* x        = (const float*)d_in[0];
    const int*   ei       = (const int*)  d_in[1];
    const float* W1       = (const float*)d_in[2];
    const float* att_src1 = (const float*)d_in[3];
    const float* att_dst1 = (const float*)d_in[4];
    const float* b1       = (const float*)d_in[5];
    const float* W2       = (const float*)d_in[6];
    const float* att_src2 = (const float*)d_in[7];
    const float* att_dst2 = (const float*)d_in[8];
    const float* b2       = (const float*)d_in[9];
    const float* lin_w    = (const float*)d_in[10];
    const float* lin_b    = (const float*)d_in[11];
    float* out = (float*)d_out;
    (void)in_sizes; (void)n_in; (void)out_size;

    const int GW = (NN * 32 + 255) / 256;

    static cudaStream_t s2 = nullptr;
    static cudaEvent_t evFork = nullptr, evJoin = nullptr;
    static bool inited = false;
    if (!inited) {
        cudaFuncSetAttribute(k_gemm1, cudaFuncAttributeMaxDynamicSharedMemorySize, GEMM1_SMEM);
        cudaStreamCreateWithFlags(&s2, cudaStreamNonBlocking);
        cudaEventCreateWithFlags(&evFork, cudaEventDisableTiming);
        cudaEventCreateWithFlags(&evJoin, cudaEventDisableTiming);
        inited = true;
    }

    // fork: gemm1 (independent of CSR) on side stream
    cudaEventRecord(evFork, 0);
    cudaStreamWaitEvent(s2, evFork, 0);
    k_gemm1<<<(NN + BM - 1) / BM, 256, GEMM1_SMEM, s2>>>(x, W1, att_src1, att_dst1);
    cudaEventRecord(evJoin, s2);

    // CSR build on stream 0 (counters zero on entry; scanBC re-zeroes)
    k_hist<<<(EE + 255) / 256, 256>>>(ei);
    k_scanA<<<SCAN_B, 256>>>();
    k_scanBC<<<SCAN_B, 256>>>();
    k_scatter<<<(ET + 255) / 256, 256>>>(ei);

    // join: gather1 needs gemm1 + CSR
    cudaStreamWaitEvent(0, evJoin, 0);
    k_gather1<<<GW, 256>>>(b1);

    // layer 2
    k_gemm2<<<(NN + 31) / 32, 256>>>(W2, att_src2, att_dst2);
    k_gather2<<<GW, 256>>>(b2, lin_w, lin_b, out);
}

// round 15
// speedup vs baseline: 1.3529x; 1.1610x over previous
#include <cuda_runtime.h>
#include <cuda_fp16.h>
#include <mma.h>
#include <math.h>
#include <cstdint>

using namespace nvcuda;

#define NN    50000
#define EE    800000
#define ET    (EE + NN)
#define IND   256
#define HID   32
#define HEADS 4
#define HH    (HEADS * HID)      // 128
#define SLOPE 0.2f

// gemm1 tiling (fp16 operands, m16n16k16)
#define BM    128
#define BK    32
#define XSTRH (BK + 8)           // 40 halves (80 B row stride)
#define WSTRH (HH + 8)           // 136 halves (272 B row stride)
#define OSTR  (HH + 4)           // 132 floats
#define GEMM1_SMEM (BM * OSTR * 4)   // 67584 B (epilogue dominates; mainloop ~19 KB)

#define SCAN_B 196               // ceil(50000/256)

// ---------------- scratch ----------------
__device__ __half d_h1h[NN * HH];   // fp16 h1 for gather
__device__ float d_as1[NN * HEADS];
__device__ float d_ad1[NN * HEADS];
__device__ float d_out1[NN * HH];

__device__ __half d_h2h[NN * HID];  // fp16 h2 for gather
__device__ float d_as2[NN];
__device__ float d_ad2[NN];

// CSR scratch: [0,NN) = histogram counts, [NN,2NN) = scatter cursors
// Both banks zero at entry (zero-init at load; scanBC re-zeroes each run).
__device__ int d_cnt   [2 * NN];
__device__ int d_rowptr[NN + 1];
__device__ int d_esrc  [ET];
__device__ int d_bsum  [256];

// ---------------- helpers ----------------
__device__ __forceinline__ float lrelu(float v) { return v > 0.0f ? v : SLOPE * v; }
__device__ __forceinline__ float eluf (float v) { return v > 0.0f ? v : __expf(v) - 1.0f; }

// ---------------- CSR build ----------------
__global__ void k_hist(const int* __restrict__ ei) {
    int e = blockIdx.x * blockDim.x + threadIdx.x;
    if (e < EE) atomicAdd(&d_cnt[ei[EE + e]], 1);
}

__global__ void k_scanA() {
    __shared__ int sh[256];
    int t = threadIdx.x;
    int idx = blockIdx.x * 256 + t;
    int c = (idx < NN) ? (d_cnt[idx] + 1) : 0;   // +1: self loop
    sh[t] = c;
    __syncthreads();
#pragma unroll
    for (int off = 1; off < 256; off <<= 1) {
        int v = (t >= off) ? sh[t - off] : 0;
        __syncthreads();
        sh[t] += v;
        __syncthreads();
    }
    if (idx < NN) d_rowptr[idx] = sh[t] - c;
    if (t == 255) d_bsum[blockIdx.x] = sh[255];
}

// fused: reduction over preceding block sums + offset add + counter re-zero
__global__ void k_scanBC() {
    __shared__ int sh[256];
    int t = threadIdx.x;
    int b = blockIdx.x;
    sh[t] = (t < b) ? d_bsum[t] : 0;    // b <= 195 < 256
    __syncthreads();
#pragma unroll
    for (int off = 128; off; off >>= 1) {
        if (t < off) sh[t] += sh[t + off];
        __syncthreads();
    }
    int pref = sh[0];
    int idx = b * 256 + t;
    if (idx < NN) {
        d_rowptr[idx] += pref;
        d_cnt[idx] = 0;          // hist bank: clean for NEXT run
        d_cnt[NN + idx] = 0;     // cursor bank: clean for scatter THIS run
    }
    if (idx == 0) d_rowptr[NN] = ET;
}

__global__ void k_scatter(const int* __restrict__ ei) {
    int id = blockIdx.x * blockDim.x + threadIdx.x;
    if (id >= ET) return;
    int s, d;
    if (id < EE) { s = ei[id]; d = ei[EE + id]; }
    else         { s = id - EE; d = id - EE; }
    int pos = d_rowptr[d] + atomicAdd(&d_cnt[NN + d], 1);
    d_esrc[pos] = s;
}

// ---------------- layer 1: FP16 wmma GEMM (m16n16k16) + attention scalars ----------------
// 256 threads = 8 warps, 4(M) x 2(N); warp tile 32x64 = 2x4 frags
__global__ void __launch_bounds__(256) k_gemm1(
        const float* __restrict__ x, const float* __restrict__ W,
        const float* __restrict__ att_s, const float* __restrict__ att_d) {
    extern __shared__ float smem[];
    __half* xs = (__half*)smem;                       // [BM][XSTRH]  10240 B
    __half* ws = (__half*)(smem + BM * XSTRH / 2);    // [BK][WSTRH]   8704 B
    float*  os = smem;                                // epilogue reuse [BM][OSTR]

    int tid  = threadIdx.x;
    int wid  = tid >> 5, lane = tid & 31;
    int n0   = blockIdx.x * BM;
    int wm   = wid & 3;
    int wn   = wid >> 2;

    wmma::fragment<wmma::accumulator, 16, 16, 16, float> c[2][4];
#pragma unroll
    for (int i = 0; i < 2; i++)
#pragma unroll
        for (int j = 0; j < 4; j++) wmma::fill_fragment(c[i][j], 0.0f);

    for (int k0 = 0; k0 < IND; k0 += BK) {
        // x tile: 128 rows x 32 cols = 1024 float4 reads -> half2 x2 stores
#pragma unroll
        for (int it = 0; it < 4; it++) {
            int i   = tid + it * 256;
            int row = i >> 3, kq = i & 7;
            int n   = n0 + row;
            float4 v = make_float4(0.f, 0.f, 0.f, 0.f);
            if (n < NN) v = *(const float4*)&x[(size_t)n * IND + k0 + kq * 4];
            __half2 h01 = __floats2half2_rn(v.x, v.y);
            __half2 h23 = __floats2half2_rn(v.z, v.w);
            *(__half2*)&xs[row * XSTRH + kq * 4 + 0] = h01;
            *(__half2*)&xs[row * XSTRH + kq * 4 + 2] = h23;
        }
        // W tile: 32 rows x 128 cols = 1024 float4 reads
#pragma unroll
        for (int it = 0; it < 4; it++) {
            int i  = tid + it * 256;
            int k  = i >> 5, nq = i & 31;
            float4 v = *(const float4*)&W[(size_t)(k0 + k) * HH + nq * 4];
            __half2 h01 = __floats2half2_rn(v.x, v.y);
            __half2 h23 = __floats2half2_rn(v.z, v.w);
            *(__half2*)&ws[k * WSTRH + nq * 4 + 0] = h01;
            *(__half2*)&ws[k * WSTRH + nq * 4 + 2] = h23;
        }
        __syncthreads();

#pragma unroll
        for (int kk = 0; kk < BK; kk += 16) {
            wmma::fragment<wmma::matrix_a, 16, 16, 16, __half, wmma::row_major> a[2];
            wmma::fragment<wmma::matrix_b, 16, 16, 16, __half, wmma::row_major> b[4];
#pragma unroll
            for (int i = 0; i < 2; i++)
                wmma::load_matrix_sync(a[i], &xs[(wm * 32 + i * 16) * XSTRH + kk], XSTRH);
#pragma unroll
            for (int j = 0; j < 4; j++)
                wmma::load_matrix_sync(b[j], &ws[kk * WSTRH + wn * 64 + j * 16], WSTRH);
#pragma unroll
            for (int i = 0; i < 2; i++)
#pragma unroll
                for (int j = 0; j < 4; j++)
                    wmma::mma_sync(c[i][j], a[i], b[j], c[i][j]);
        }
        __syncthreads();
    }

    // stage accumulators in smem (xs/ws dead)
#pragma unroll
    for (int i = 0; i < 2; i++)
#pragma unroll
        for (int j = 0; j < 4; j++)
            wmma::store_matrix_sync(&os[(wm * 32 + i * 16) * OSTR + wn * 64 + j * 16],
                                    c[i][j], OSTR, wmma::mem_row_major);
    __syncthreads();

    // epilogue: fp16 h1 write + attention scalars
    int head = wid & 3;
    int rofs = wid >> 2;
    float es = att_s[head * HID + lane];
    float ed = att_d[head * HID + lane];
#pragma unroll 4
    for (int r2 = 0; r2 < BM; r2 += 2) {
        int r = r2 + rofs;
        int n = n0 + r;
        if (n >= NN) continue;
        float v = os[r * OSTR + head * 32 + lane];
        d_h1h[(size_t)n * HH + head * 32 + lane] = __float2half_rn(v);
        float s = v * es, t = v * ed;
#pragma unroll
        for (int o = 16; o; o >>= 1) {
            s += __shfl_xor_sync(0xffffffffu, s, o);
            t += __shfl_xor_sync(0xffffffffu, t, o);
        }
        if (lane == 0) { d_as1[n * HEADS + head] = s; d_ad1[n * HEADS + head] = t; }
    }
}

// ---------------- layer 1: CSR gather (fp16 rows, chunked shuffle) ----------------
__global__ void k_gather1(const float* __restrict__ b1) {
    int gid  = blockIdx.x * blockDim.x + threadIdx.x;
    int n    = gid >> 5;
    if (n >= NN) return;
    int lane = gid & 31;
    int h    = lane >> 3;

    int start = d_rowptr[n], end = d_rowptr[n + 1];
    float ad = d_ad1[n * 4 + h];

    float4 acc = make_float4(0.f, 0.f, 0.f, 0.f);
    float  den = 0.f;

    for (int base = start; base < end; base += 32) {
        int m   = min(32, end - base);
        int myS = (lane < m) ? __ldg(&d_esrc[base + lane]) : 0;
#pragma unroll 4
        for (int i = 0; i < m; i++) {
            int s = __shfl_sync(0xffffffffu, myS, i);
            float p = __expf(lrelu(__ldg(&d_as1[s * 4 + h]) + ad));
            uint2 raw = *(const uint2*)&d_h1h[(size_t)s * HH + lane * 4];
            float2 f01 = __half22float2(*(__half2*)&raw.x);
            float2 f23 = __half22float2(*(__half2*)&raw.y);
            den  += p;
            acc.x = fmaf(p, f01.x, acc.x);
            acc.y = fmaf(p, f01.y, acc.y);
            acc.z = fmaf(p, f23.x, acc.z);
            acc.w = fmaf(p, f23.y, acc.w);
        }
    }

    float inv = 1.0f / den;
    float4 bb = *(const float4*)&b1[lane * 4];
    acc.x = eluf(acc.x * inv + bb.x);
    acc.y = eluf(acc.y * inv + bb.y);
    acc.z = eluf(acc.z * inv + bb.z);
    acc.w = eluf(acc.w * inv + bb.w);
    *(float4*)&d_out1[(size_t)n * HH + lane * 4] = acc;
}

// ---------------- layer 2: GEMM (32 nodes/block) + attention scalars ----------------
__global__ void k_gemm2(const float* __restrict__ W2,
                        const float* __restrict__ att_s, const float* __restrict__ att_d) {
    __shared__ float Ws[HH * HID];    // 16 KB
    __shared__ float xs[32][HH];      // 16 KB
    int tid = threadIdx.x;
    for (int t = tid; t < HH * HID; t += 256) Ws[t] = W2[t];
    int w = tid >> 5, lane = tid & 31;
    int n0 = blockIdx.x * 32;
#pragma unroll
    for (int r = 0; r < 4; r++) {
        int row = w * 4 + r;
        int n = n0 + row;
        if (n < NN)
            *(float4*)&xs[row][lane * 4] = *(const float4*)&d_out1[(size_t)n * HH + lane * 4];
    }
    __syncthreads();

    float as_l = att_s[lane], ad_l = att_d[lane];
#pragma unroll
    for (int r = 0; r < 4; r++) {
        int row = w * 4 + r;
        int n = n0 + row;
        if (n >= NN) break;
        float acc = 0.0f;
#pragma unroll 8
        for (int k = 0; k < HH; k += 4) {
            float4 xv = *(const float4*)&xs[row][k];
            acc += xv.x * Ws[(k + 0) * HID + lane];
            acc += xv.y * Ws[(k + 1) * HID + lane];
            acc += xv.z * Ws[(k + 2) * HID + lane];
            acc += xv.w * Ws[(k + 3) * HID + lane];
        }
        d_h2h[n * HID + lane] = __float2half_rn(acc);
        float s = acc * as_l, t = acc * ad_l;
#pragma unroll
        for (int o = 16; o; o >>= 1) {
            s += __shfl_xor_sync(0xffffffffu, s, o);
            t += __shfl_xor_sync(0xffffffffu, t, o);
        }
        if (lane == 0) { d_as2[n] = s; d_ad2[n] = t; }
    }
}

// ---------------- layer 2: CSR gather + bias/ELU + classifier ----------------
__global__ void k_gather2(const float* __restrict__ b2, const float* __restrict__ lw,
                          const float* __restrict__ lb, float* __restrict__ out) {
    int gid  = blockIdx.x * blockDim.x + threadIdx.x;
    int n    = gid >> 5;
    if (n >= NN) return;
    int lane = gid & 31;

    int start = d_rowptr[n], end = d_rowptr[n + 1];
    float ad = d_ad2[n];

    float acc = 0.f, den = 0.f;
    for (int base = start; base < end; base += 32) {
        int m   = min(32, end - base);
        int myS = (lane < m) ? __ldg(&d_esrc[base + lane]) : 0;
        float myA = (lane < m) ? __ldg(&d_as2[myS]) : 0.f;
#pragma unroll 4
        for (int i = 0; i < m; i++) {
            int   s  = __shfl_sync(0xffffffffu, myS, i);
            float as = __shfl_sync(0xffffffffu, myA, i);
            float p  = __expf(lrelu(as + ad));
            den += p;
            acc = fmaf(p, __half2float(d_h2h[s * HID + lane]), acc);
        }
    }

    float v = eluf(acc / den + b2[lane]);
    float o0 = v * lw[lane * 2 + 0];
    float o1 = v * lw[lane * 2 + 1];
#pragma unroll
    for (int o = 16; o; o >>= 1) {
        o0 += __shfl_xor_sync(0xffffffffu, o0, o);
        o1 += __shfl_xor_sync(0xffffffffu, o1, o);
    }
    if (lane == 0) { out[n * 2 + 0] = o0 + lb[0]; out[n * 2 + 1] = o1 + lb[1]; }
}

// ---------------- launch ----------------
extern "C" void kernel_launch(void* const* d_in, const int* in_sizes, int n_in,
                              void* d_out, int out_size) {
    const float* x        = (const float*)d_in[0];
    const int*   ei       = (const int*)  d_in[1];
    const float* W1       = (const float*)d_in[2];
    const float* att_src1 = (const float*)d_in[3];
    const float* att_dst1 = (const float*)d_in[4];
    const float* b1       = (const float*)d_in[5];
    const float* W2       = (const float*)d_in[6];
    const float* att_src2 = (const float*)d_in[7];
    const float* att_dst2 = (const float*)d_in[8];
    const float* b2       = (const float*)d_in[9];
    const float* lin_w    = (const float*)d_in[10];
    const float* lin_b    = (const float*)d_in[11];
    float* out = (float*)d_out;
    (void)in_sizes; (void)n_in; (void)out_size;

    const int GW = (NN * 32 + 255) / 256;

    static cudaStream_t s2 = nullptr;
    static cudaEvent_t evFork = nullptr, evJoin = nullptr;
    static bool inited = false;
    if (!inited) {
        cudaFuncSetAttribute(k_gemm1, cudaFuncAttributeMaxDynamicSharedMemorySize, GEMM1_SMEM);
        cudaStreamCreateWithFlags(&s2, cudaStreamNonBlocking);
        cudaEventCreateWithFlags(&evFork, cudaEventDisableTiming);
        cudaEventCreateWithFlags(&evJoin, cudaEventDisableTiming);
        inited = true;
    }

    // fork: gemm1 (independent of CSR) on side stream
    cudaEventRecord(evFork, 0);
    cudaStreamWaitEvent(s2, evFork, 0);
    k_gemm1<<<(NN + BM - 1) / BM, 256, GEMM1_SMEM, s2>>>(x, W1, att_src1, att_dst1);
    cudaEventRecord(evJoin, s2);

    // CSR build on stream 0 (counters zero on entry; scanBC re-zeroes)
    k_hist<<<(EE + 255) / 256, 256>>>(ei);
    k_scanA<<<SCAN_B, 256>>>();
    k_scanBC<<<SCAN_B, 256>>>();
    k_scatter<<<(ET + 255) / 256, 256>>>(ei);

    // join: gather1 needs gemm1 + CSR
    cudaStreamWaitEvent(0, evJoin, 0);
    k_gather1<<<GW, 256>>>(b1);

    // layer 2
    k_gemm2<<<(NN + 31) / 32, 256>>>(W2, att_src2, att_dst2);
    k_gather2<<<GW, 256>>>(b2, lin_w, lin_b, out);
}

// round 16
// speedup vs baseline: 1.4355x; 1.0611x over previous
#include <cuda_runtime.h>
#include <cuda_fp16.h>
#include <mma.h>
#include <math.h>
#include <cstdint>

using namespace nvcuda;

#define NN    50000
#define EE    800000
#define ET    (EE + NN)
#define IND   256
#define HID   32
#define HEADS 4
#define HH    (HEADS * HID)      // 128
#define SLOPE 0.2f

// gemm1 tiling (fp16 operands, m16n16k16)
#define BM    128
#define BK    32
#define XSTRH (BK + 8)           // 40 halves
#define WSTRH (HH + 8)           // 136 halves
#define OSTR  (HH + 4)           // 132 floats
#define GEMM1_SMEM (BM * OSTR * 4)   // 67584 B

#define SCAN_B 196               // ceil(50000/256)

// ---------------- scratch ----------------
__device__ __half d_h1h[NN * HH];   // fp16 h1 for gather
__device__ float d_as1[NN * HEADS];
__device__ float d_ad1[NN * HEADS];

__device__ __half d_h2h[NN * HID];  // fp16 h2 for gather
__device__ float d_as2[NN];
__device__ float d_ad2[NN];

// CSR scratch: [0,NN) = histogram counts, [NN,2NN) = scatter cursors
// Both banks zero at entry (zero-init at load; scanBC re-zeroes each run).
__device__ int d_cnt   [2 * NN];
__device__ int d_rowptr[NN + 1];
__device__ int d_esrc  [ET];
__device__ int d_bsum  [256];

// ---------------- helpers ----------------
__device__ __forceinline__ float lrelu(float v) { return v > 0.0f ? v : SLOPE * v; }
__device__ __forceinline__ float eluf (float v) { return v > 0.0f ? v : __expf(v) - 1.0f; }

// ---------------- CSR build ----------------
__global__ void k_hist(const int* __restrict__ ei) {
    int e = blockIdx.x * blockDim.x + threadIdx.x;
    if (e < EE) atomicAdd(&d_cnt[ei[EE + e]], 1);
}

__global__ void k_scanA() {
    __shared__ int sh[256];
    int t = threadIdx.x;
    int idx = blockIdx.x * 256 + t;
    int c = (idx < NN) ? (d_cnt[idx] + 1) : 0;   // +1: self loop
    sh[t] = c;
    __syncthreads();
#pragma unroll
    for (int off = 1; off < 256; off <<= 1) {
        int v = (t >= off) ? sh[t - off] : 0;
        __syncthreads();
        sh[t] += v;
        __syncthreads();
    }
    if (idx < NN) d_rowptr[idx] = sh[t] - c;
    if (t == 255) d_bsum[blockIdx.x] = sh[255];
}

// fused: reduction over preceding block sums + offset add + counter re-zero
__global__ void k_scanBC() {
    __shared__ int sh[256];
    int t = threadIdx.x;
    int b = blockIdx.x;
    sh[t] = (t < b) ? d_bsum[t] : 0;    // b <= 195 < 256
    __syncthreads();
#pragma unroll
    for (int off = 128; off; off >>= 1) {
        if (t < off) sh[t] += sh[t + off];
        __syncthreads();
    }
    int pref = sh[0];
    int idx = b * 256 + t;
    if (idx < NN) {
        d_rowptr[idx] += pref;
        d_cnt[idx] = 0;          // hist bank: clean for NEXT run
        d_cnt[NN + idx] = 0;     // cursor bank: clean for scatter THIS run
    }
    if (idx == 0) d_rowptr[NN] = ET;
}

__global__ void k_scatter(const int* __restrict__ ei) {
    int id = blockIdx.x * blockDim.x + threadIdx.x;
    if (id >= ET) return;
    int s, d;
    if (id < EE) { s = ei[id]; d = ei[EE + id]; }
    else         { s = id - EE; d = id - EE; }
    int pos = d_rowptr[d] + atomicAdd(&d_cnt[NN + d], 1);
    d_esrc[pos] = s;
}

// ---------------- layer 1: FP16 wmma GEMM (m16n16k16) + attention scalars ----------------
// 256 threads = 8 warps, 4(M) x 2(N); warp tile 32x64 = 2x4 frags
__global__ void __launch_bounds__(256) k_gemm1(
        const float* __restrict__ x, const float* __restrict__ W,
        const float* __restrict__ att_s, const float* __restrict__ att_d) {
    extern __shared__ float smem[];
    __half* xs = (__half*)smem;                       // [BM][XSTRH]
    __half* ws = (__half*)(smem + BM * XSTRH / 2);    // [BK][WSTRH]
    float*  os = smem;                                // epilogue reuse [BM][OSTR]

    int tid  = threadIdx.x;
    int wid  = tid >> 5, lane = tid & 31;
    int n0   = blockIdx.x * BM;
    int wm   = wid & 3;
    int wn   = wid >> 2;

    wmma::fragment<wmma::accumulator, 16, 16, 16, float> c[2][4];
#pragma unroll
    for (int i = 0; i < 2; i++)
#pragma unroll
        for (int j = 0; j < 4; j++) wmma::fill_fragment(c[i][j], 0.0f);

    for (int k0 = 0; k0 < IND; k0 += BK) {
#pragma unroll
        for (int it = 0; it < 4; it++) {
            int i   = tid + it * 256;
            int row = i >> 3, kq = i & 7;
            int n   = n0 + row;
            float4 v = make_float4(0.f, 0.f, 0.f, 0.f);
            if (n < NN) v = *(const float4*)&x[(size_t)n * IND + k0 + kq * 4];
            __half2 h01 = __floats2half2_rn(v.x, v.y);
            __half2 h23 = __floats2half2_rn(v.z, v.w);
            *(__half2*)&xs[row * XSTRH + kq * 4 + 0] = h01;
            *(__half2*)&xs[row * XSTRH + kq * 4 + 2] = h23;
        }
#pragma unroll
        for (int it = 0; it < 4; it++) {
            int i  = tid + it * 256;
            int k  = i >> 5, nq = i & 31;
            float4 v = *(const float4*)&W[(size_t)(k0 + k) * HH + nq * 4];
            __half2 h01 = __floats2half2_rn(v.x, v.y);
            __half2 h23 = __floats2half2_rn(v.z, v.w);
            *(__half2*)&ws[k * WSTRH + nq * 4 + 0] = h01;
            *(__half2*)&ws[k * WSTRH + nq * 4 + 2] = h23;
        }
        __syncthreads();

#pragma unroll
        for (int kk = 0; kk < BK; kk += 16) {
            wmma::fragment<wmma::matrix_a, 16, 16, 16, __half, wmma::row_major> a[2];
            wmma::fragment<wmma::matrix_b, 16, 16, 16, __half, wmma::row_major> b[4];
#pragma unroll
            for (int i = 0; i < 2; i++)
                wmma::load_matrix_sync(a[i], &xs[(wm * 32 + i * 16) * XSTRH + kk], XSTRH);
#pragma unroll
            for (int j = 0; j < 4; j++)
                wmma::load_matrix_sync(b[j], &ws[kk * WSTRH + wn * 64 + j * 16], WSTRH);
#pragma unroll
            for (int i = 0; i < 2; i++)
#pragma unroll
                for (int j = 0; j < 4; j++)
                    wmma::mma_sync(c[i][j], a[i], b[j], c[i][j]);
        }
        __syncthreads();
    }

#pragma unroll
    for (int i = 0; i < 2; i++)
#pragma unroll
        for (int j = 0; j < 4; j++)
            wmma::store_matrix_sync(&os[(wm * 32 + i * 16) * OSTR + wn * 64 + j * 16],
                                    c[i][j], OSTR, wmma::mem_row_major);
    __syncthreads();

    int head = wid & 3;
    int rofs = wid >> 2;
    float es = att_s[head * HID + lane];
    float ed = att_d[head * HID + lane];
#pragma unroll 4
    for (int r2 = 0; r2 < BM; r2 += 2) {
        int r = r2 + rofs;
        int n = n0 + r;
        if (n >= NN) continue;
        float v = os[r * OSTR + head * 32 + lane];
        d_h1h[(size_t)n * HH + head * 32 + lane] = __float2half_rn(v);
        float s = v * es, t = v * ed;
#pragma unroll
        for (int o = 16; o; o >>= 1) {
            s += __shfl_xor_sync(0xffffffffu, s, o);
            t += __shfl_xor_sync(0xffffffffu, t, o);
        }
        if (lane == 0) { d_as1[n * HEADS + head] = s; d_ad1[n * HEADS + head] = t; }
    }
}

// ---------------- FUSED: layer-1 gather (softmax agg + bias + ELU) + layer-2 GEMM ----------------
// 256 threads = 8 warps; 32 nodes/block; each warp gathers 4 nodes into smem,
// then computes h2 + attention scalars for the same 4 nodes.
__global__ void __launch_bounds__(256) k_fuse(
        const float* __restrict__ b1, const float* __restrict__ W2,
        const float* __restrict__ att_s2, const float* __restrict__ att_d2) {
    __shared__ float Ws[HH * HID];    // 16 KB
    __shared__ float xs[32][HH];      // 16 KB
    int tid = threadIdx.x;
    int w = tid >> 5, lane = tid & 31;
    int n0 = blockIdx.x * 32;

    // preload W2 (hidden under gather latency of warp 0's first loads)
    for (int t = tid; t < HH * HID; t += 256) Ws[t] = W2[t];

    int h = lane >> 3;
    float4 bb = *(const float4*)&b1[lane * 4];

    // gather phase: each warp aggregates 4 nodes
#pragma unroll
    for (int r = 0; r < 4; r++) {
        int row = w * 4 + r;
        int n = n0 + row;
        if (n >= NN) break;

        int start = d_rowptr[n], end = d_rowptr[n + 1];
        float ad = d_ad1[n * 4 + h];

        float4 acc = make_float4(0.f, 0.f, 0.f, 0.f);
        float  den = 0.f;

        for (int base = start; base < end; base += 32) {
            int m   = min(32, end - base);
            int myS = (lane < m) ? __ldg(&d_esrc[base + lane]) : 0;
#pragma unroll 4
            for (int i = 0; i < m; i++) {
                int s = __shfl_sync(0xffffffffu, myS, i);
                float p = __expf(lrelu(__ldg(&d_as1[s * 4 + h]) + ad));
                uint2 raw = *(const uint2*)&d_h1h[(size_t)s * HH + lane * 4];
                float2 f01 = __half22float2(*(__half2*)&raw.x);
                float2 f23 = __half22float2(*(__half2*)&raw.y);
                den  += p;
                acc.x = fmaf(p, f01.x, acc.x);
                acc.y = fmaf(p, f01.y, acc.y);
                acc.z = fmaf(p, f23.x, acc.z);
                acc.w = fmaf(p, f23.y, acc.w);
            }
        }

        float inv = 1.0f / den;
        acc.x = eluf(acc.x * inv + bb.x);
        acc.y = eluf(acc.y * inv + bb.y);
        acc.z = eluf(acc.z * inv + bb.z);
        acc.w = eluf(acc.w * inv + bb.w);
        *(float4*)&xs[row][lane * 4] = acc;
    }
    __syncthreads();

    // gemm2 phase: h2 = xs . W2, attention scalars
    float as_l = att_s2[lane], ad_l = att_d2[lane];
#pragma unroll
    for (int r = 0; r < 4; r++) {
        int row = w * 4 + r;
        int n = n0 + row;
        if (n >= NN) break;
        float acc = 0.0f;
#pragma unroll 8
        for (int k = 0; k < HH; k += 4) {
            float4 xv = *(const float4*)&xs[row][k];
            acc += xv.x * Ws[(k + 0) * HID + lane];
            acc += xv.y * Ws[(k + 1) * HID + lane];
            acc += xv.z * Ws[(k + 2) * HID + lane];
            acc += xv.w * Ws[(k + 3) * HID + lane];
        }
        d_h2h[n * HID + lane] = __float2half_rn(acc);
        float s = acc * as_l, t = acc * ad_l;
#pragma unroll
        for (int o = 16; o; o >>= 1) {
            s += __shfl_xor_sync(0xffffffffu, s, o);
            t += __shfl_xor_sync(0xffffffffu, t, o);
        }
        if (lane == 0) { d_as2[n] = s; d_ad2[n] = t; }
    }
}

// ---------------- layer 2: CSR gather + bias/ELU + classifier ----------------
__global__ void k_gather2(const float* __restrict__ b2, const float* __restrict__ lw,
                          const float* __restrict__ lb, float* __restrict__ out) {
    int gid  = blockIdx.x * blockDim.x + threadIdx.x;
    int n    = gid >> 5;
    if (n >= NN) return;
    int lane = gid & 31;

    int start = d_rowptr[n], end = d_rowptr[n + 1];
    float ad = d_ad2[n];

    float acc = 0.f, den = 0.f;
    for (int base = start; base < end; base += 32) {
        int m   = min(32, end - base);
        int myS = (lane < m) ? __ldg(&d_esrc[base + lane]) : 0;
        float myA = (lane < m) ? __ldg(&d_as2[myS]) : 0.f;
#pragma unroll 4
        for (int i = 0; i < m; i++) {
            int   s  = __shfl_sync(0xffffffffu, myS, i);
            float as = __shfl_sync(0xffffffffu, myA, i);
            float p  = __expf(lrelu(as + ad));
            den += p;
            acc = fmaf(p, __half2float(d_h2h[s * HID + lane]), acc);
        }
    }

    float v = eluf(acc / den + b2[lane]);
    float o0 = v * lw[lane * 2 + 0];
    float o1 = v * lw[lane * 2 + 1];
#pragma unroll
    for (int o = 16; o; o >>= 1) {
        o0 += __shfl_xor_sync(0xffffffffu, o0, o);
        o1 += __shfl_xor_sync(0xffffffffu, o1, o);
    }
    if (lane == 0) { out[n * 2 + 0] = o0 + lb[0]; out[n * 2 + 1] = o1 + lb[1]; }
}

// ---------------- launch ----------------
extern "C" void kernel_launch(void* const* d_in, const int* in_sizes, int n_in,
                              void* d_out, int out_size) {
    const float* x        = (const float*)d_in[0];
    const int*   ei       = (const int*)  d_in[1];
    const float* W1       = (const float*)d_in[2];
    const float* att_src1 = (const float*)d_in[3];
    const float* att_dst1 = (const float*)d_in[4];
    const float* b1       = (const float*)d_in[5];
    const float* W2       = (const float*)d_in[6];
    const float* att_src2 = (const float*)d_in[7];
    const float* att_dst2 = (const float*)d_in[8];
    const float* b2       = (const float*)d_in[9];
    const float* lin_w    = (const float*)d_in[10];
    const float* lin_b    = (const float*)d_in[11];
    float* out = (float*)d_out;
    (void)in_sizes; (void)n_in; (void)out_size;

    const int GW = (NN * 32 + 255) / 256;

    static cudaStream_t s2 = nullptr;
    static cudaEvent_t evFork = nullptr, evJoin = nullptr;
    static bool inited = false;
    if (!inited) {
        cudaFuncSetAttribute(k_gemm1, cudaFuncAttributeMaxDynamicSharedMemorySize, GEMM1_SMEM);
        cudaStreamCreateWithFlags(&s2, cudaStreamNonBlocking);
        cudaEventCreateWithFlags(&evFork, cudaEventDisableTiming);
        cudaEventCreateWithFlags(&evJoin, cudaEventDisableTiming);
        inited = true;
    }

    // fork: gemm1 (independent of CSR) on side stream
    cudaEventRecord(evFork, 0);
    cudaStreamWaitEvent(s2, evFork, 0);
    k_gemm1<<<(NN + BM - 1) / BM, 256, GEMM1_SMEM, s2>>>(x, W1, att_src1, att_dst1);
    cudaEventRecord(evJoin, s2);

    // CSR build on stream 0 (counters zero on entry; scanBC re-zeroes)
    k_hist<<<(EE + 255) / 256, 256>>>(ei);
    k_scanA<<<SCAN_B, 256>>>();
    k_scanBC<<<SCAN_B, 256>>>();
    k_scatter<<<(ET + 255) / 256, 256>>>(ei);

    // join: fused gather1+gemm2 needs gemm1 + CSR
    cudaStreamWaitEvent(0, evJoin, 0);
    k_fuse<<<(NN + 31) / 32, 256>>>(b1, W2, att_src2, att_dst2);

    // layer 2 gather + classifier
    k_gather2<<<GW, 256>>>(b2, lin_w, lin_b, out);
}